// round 16
// baseline (speedup 1.0000x reference)
#include <cuda_runtime.h>
#include <cuda_bf16.h>
#include <cuda_pipeline.h>

// Problem constants (Swin window attention)
#define WIN    7
#define NTOK   49
#define DIM    512
#define HEADS  16
#define HD     32
#define BW     2048
#define M_TOT  (BW * NTOK)   // 100352
#define THREEC 1536
#define NSQ    (NTOK * NTOK) // 2401

#define BK     16
#define NCH    (DIM / BK)    // 32 K-chunks

// Scratch (allocation-free: __device__ globals)
__device__ float g_q[BW * HEADS * NTOK * HD];
__device__ float g_k[BW * HEADS * NTOK * HD];
__device__ float g_v[BW * HEADS * NTOK * HD];
__device__ float g_att[M_TOT * DIM];
__device__ float g_bias[HEADS * NSQ];      // precomputed rpb[rel[nm]*16+h]

// ---------------------------------------------------------------------------
// Kernel 0: bias precompute. g_bias[h][nm] = rpb[rel[nm]*HEADS + h].
// ---------------------------------------------------------------------------
__global__ void bias_precompute(const float* __restrict__ rpb,
                                const int* __restrict__ rel) {
    int t = blockIdx.x * 256 + threadIdx.x;
    if (t < HEADS * NSQ) {
        int h  = t / NSQ;
        int nm = t - h * NSQ;
        g_bias[t] = rpb[rel[nm] * HEADS + h];
    }
}

// ---------------------------------------------------------------------------
// Kernel 1: QKV GEMM. Double-buffered BK=16; B staged via cp.async
// (__pipeline_memcpy_async, 16B granules matching the permuted layout);
// A register-staged (needs transpose). Vectorized scatter epilogue.
// ---------------------------------------------------------------------------
__global__ __launch_bounds__(256) void qkv_gemm_db(const float* __restrict__ A,
                                                   const float* __restrict__ B,
                                                   const float* __restrict__ bias) {
    __shared__ __align__(16) float As[2][BK][128];
    __shared__ __align__(16) float Bs[2][BK][128];   // permuted

    const int tid  = threadIdx.x;
    const int lane = tid & 31;
    const int warp = tid >> 5;
    const int tRow = (warp >> 1) * 4 + (lane >> 3);
    const int tCol = (warp & 1) * 8 + (lane & 7);
    const int wn   = warp & 1;
    const int cc   = lane & 7;

    const int ar = tid >> 1;
    const int ac = (tid & 1) << 3;
    const int bk = tid >> 4;
    const int bc = (tid & 15) << 3;
    const int bpo = ((bc >> 6) << 6) | (((bc >> 3) & 7) << 2);

    const float* Abase = A + (size_t)blockIdx.y * 128 * DIM + (size_t)ar * DIM + ac;
    const float* Bbase = B + (size_t)bk * THREEC + blockIdx.x * 128 + bc;

    float acc[8][8];
#pragma unroll
    for (int i = 0; i < 8; i++)
#pragma unroll
        for (int j = 0; j < 8; j++) acc[i][j] = 0.f;

    // ---- prologue: chunk 0 ----
    {
        __pipeline_memcpy_async(&Bs[0][bk][bpo],      Bbase,     16);
        __pipeline_memcpy_async(&Bs[0][bk][bpo + 32], Bbase + 4, 16);
        __pipeline_commit();
        float4 a0 = *(const float4*)(Abase);
        float4 a1 = *(const float4*)(Abase + 4);
        As[0][ac + 0][ar] = a0.x; As[0][ac + 1][ar] = a0.y;
        As[0][ac + 2][ar] = a0.z; As[0][ac + 3][ar] = a0.w;
        As[0][ac + 4][ar] = a1.x; As[0][ac + 5][ar] = a1.y;
        As[0][ac + 6][ar] = a1.z; As[0][ac + 7][ar] = a1.w;
        __pipeline_wait_prior(0);
    }
    __syncthreads();

    for (int ch = 0; ch < NCH; ch++) {
        const int cb = ch & 1;
        const int nb = cb ^ 1;

        float4 pa0, pa1;
        if (ch + 1 < NCH) {
            // async B copy for next chunk overlaps this chunk's compute
            const float* bsrc = Bbase + (size_t)(ch + 1) * BK * THREEC;
            __pipeline_memcpy_async(&Bs[nb][bk][bpo],      bsrc,     16);
            __pipeline_memcpy_async(&Bs[nb][bk][bpo + 32], bsrc + 4, 16);
            __pipeline_commit();
            pa0 = *(const float4*)(Abase + (ch + 1) * BK);
            pa1 = *(const float4*)(Abase + (ch + 1) * BK + 4);
        }

#pragma unroll
        for (int k = 0; k < BK; k++) {
            float rM[8], rN[8];
            float4 m0 = *(const float4*)&As[cb][k][tRow * 8];
            float4 m1 = *(const float4*)&As[cb][k][tRow * 8 + 4];
            float4 n0 = *(const float4*)&Bs[cb][k][wn * 64 + cc * 4];
            float4 n1 = *(const float4*)&Bs[cb][k][wn * 64 + 32 + cc * 4];
            rM[0] = m0.x; rM[1] = m0.y; rM[2] = m0.z; rM[3] = m0.w;
            rM[4] = m1.x; rM[5] = m1.y; rM[6] = m1.z; rM[7] = m1.w;
            rN[0] = n0.x; rN[1] = n0.y; rN[2] = n0.z; rN[3] = n0.w;
            rN[4] = n1.x; rN[5] = n1.y; rN[6] = n1.z; rN[7] = n1.w;
#pragma unroll
            for (int i = 0; i < 8; i++)
#pragma unroll
                for (int j = 0; j < 8; j++) acc[i][j] += rM[i] * rN[j];
        }

        if (ch + 1 < NCH) {
            As[nb][ac + 0][ar] = pa0.x; As[nb][ac + 1][ar] = pa0.y;
            As[nb][ac + 2][ar] = pa0.z; As[nb][ac + 3][ar] = pa0.w;
            As[nb][ac + 4][ar] = pa1.x; As[nb][ac + 5][ar] = pa1.y;
            As[nb][ac + 6][ar] = pa1.z; As[nb][ac + 7][ar] = pa1.w;
            __pipeline_wait_prior(0);
        }
        __syncthreads();
    }

    // ---- vectorized scatter epilogue ----
    const float scale = 0.17677669529663687f;  // 32^-0.5
    const int col0 = blockIdx.x * 128 + tCol * 8;
    const int s    = col0 >> 9;
    const int rem  = col0 & 511;
    const int hh   = rem >> 5;
    const int dd0  = rem & 31;
    float4 bx = *(const float4*)&bias[col0];
    float4 by = *(const float4*)&bias[col0 + 4];

#pragma unroll
    for (int i = 0; i < 8; i++) {
        int row = blockIdx.y * 128 + tRow * 8 + i;
        int b = row / NTOK;
        int n = row - b * NTOK;
        float4 v0 = make_float4(acc[i][0] + bx.x, acc[i][1] + bx.y,
                                acc[i][2] + bx.z, acc[i][3] + bx.w);
        float4 v1 = make_float4(acc[i][4] + by.x, acc[i][5] + by.y,
                                acc[i][6] + by.z, acc[i][7] + by.w);
        int idx = (((b * HEADS + hh) * NTOK) + n) * HD + dd0;
        if (s == 0) {
            v0.x *= scale; v0.y *= scale; v0.z *= scale; v0.w *= scale;
            v1.x *= scale; v1.y *= scale; v1.z *= scale; v1.w *= scale;
            *(float4*)&g_q[idx] = v0;
            *(float4*)&g_q[idx + 4] = v1;
        } else if (s == 1) {
            *(float4*)&g_k[idx] = v0;
            *(float4*)&g_k[idx + 4] = v1;
        } else {
            *(float4*)&g_v[idx] = v0;
            *(float4*)&g_v[idx + 4] = v1;
        }
    }
}

// ---------------------------------------------------------------------------
// Kernel 2: attention (unchanged from round 15 — proven).
// ---------------------------------------------------------------------------
__global__ __launch_bounds__(256) void attn_kernel() {
    __shared__ __align__(16) float qs[NTOK * HD];
    __shared__ __align__(16) float kst[HD][52];
    __shared__ __align__(16) float vs[NTOK * HD];
    __shared__ __align__(16) float S[NTOK][52];

    const int bh  = blockIdx.x;
    const int h   = bh & (HEADS - 1);
    const int b   = bh >> 4;
    const int tid = threadIdx.x;
    const float* bias_h = g_bias + h * NSQ;

    const int base = bh * NTOK * HD;
    for (int i = tid; i < NTOK * HD; i += 256) {
        int n = i >> 5;
        int d = i & 31;
        qs[i] = g_q[base + i];
        kst[d][n] = g_k[base + i];
        vs[i] = g_v[base + i];
    }
    if (tid < 128) {
        int d = tid >> 2;
        int c = tid & 3;
        if (c < 3) kst[d][49 + c] = 0.f;
    }
    __syncthreads();

    for (int t = tid; t < 325; t += 256) {
        int n0 = (t / 13) * 2;
        int m0 = (t % 13) * 4;
        bool n1ok = (n0 + 1 < NTOK);
        int n1 = n1ok ? n0 + 1 : n0;
        float a0[4] = {0.f, 0.f, 0.f, 0.f};
        float a1[4] = {0.f, 0.f, 0.f, 0.f};
#pragma unroll
        for (int d0 = 0; d0 < HD; d0 += 4) {
            float4 qa = *(const float4*)&qs[n0 * HD + d0];
            float4 qb = *(const float4*)&qs[n1 * HD + d0];
            float4 k0 = *(const float4*)&kst[d0 + 0][m0];
            float4 k1 = *(const float4*)&kst[d0 + 1][m0];
            float4 k2 = *(const float4*)&kst[d0 + 2][m0];
            float4 k3 = *(const float4*)&kst[d0 + 3][m0];
            a0[0] += qa.x * k0.x + qa.y * k1.x + qa.z * k2.x + qa.w * k3.x;
            a0[1] += qa.x * k0.y + qa.y * k1.y + qa.z * k2.y + qa.w * k3.y;
            a0[2] += qa.x * k0.z + qa.y * k1.z + qa.z * k2.z + qa.w * k3.z;
            a0[3] += qa.x * k0.w + qa.y * k1.w + qa.z * k2.w + qa.w * k3.w;
            a1[0] += qb.x * k0.x + qb.y * k1.x + qb.z * k2.x + qb.w * k3.x;
            a1[1] += qb.x * k0.y + qb.y * k1.y + qb.z * k2.y + qb.w * k3.y;
            a1[2] += qb.x * k0.z + qb.y * k1.z + qb.z * k2.z + qb.w * k3.z;
            a1[3] += qb.x * k0.w + qb.y * k1.w + qb.z * k2.w + qb.w * k3.w;
        }
#pragma unroll
        for (int j = 0; j < 4; j++) {
            int m = m0 + j;
            if (m < NTOK) {
                S[n0][m] = a0[j] + bias_h[n0 * NTOK + m];
                if (n1ok)
                    S[n0 + 1][m] = a1[j] + bias_h[(n0 + 1) * NTOK + m];
            }
        }
    }
    __syncthreads();

    {
        const int warp = tid >> 5;
        const int lane = tid & 31;
        for (int n = warp; n < NTOK; n += 8) {
            float v0 = S[n][lane];
            bool hi = (lane + 32 < NTOK);
            float v1 = hi ? S[n][lane + 32] : -1e30f;
            float mx = fmaxf(v0, v1);
#pragma unroll
            for (int o = 16; o; o >>= 1) mx = fmaxf(mx, __shfl_xor_sync(0xffffffffu, mx, o));
            float e0 = __expf(v0 - mx);
            float e1 = hi ? __expf(v1 - mx) : 0.f;
            float sum = e0 + e1;
#pragma unroll
            for (int o = 16; o; o >>= 1) sum += __shfl_xor_sync(0xffffffffu, sum, o);
            float inv = 1.f / sum;
            S[n][lane] = e0 * inv;
            if (hi) S[n][lane + 32] = e1 * inv;
        }
    }
    __syncthreads();

    if (tid < 200) {
        int n0 = (tid >> 3) * 2;
        int d0 = (tid & 7) << 2;
        bool n1ok = (n0 + 1 < NTOK);
        int n1 = n1ok ? n0 + 1 : n0;
        float4 acc0 = make_float4(0.f, 0.f, 0.f, 0.f);
        float4 acc1 = acc0;
#pragma unroll 4
        for (int m4 = 0; m4 < 48; m4 += 4) {
            float4 s0 = *(const float4*)&S[n0][m4];
            float4 s1 = *(const float4*)&S[n1][m4];
            float4 v0 = *(const float4*)&vs[(m4 + 0) * HD + d0];
            float4 v1 = *(const float4*)&vs[(m4 + 1) * HD + d0];
            float4 v2 = *(const float4*)&vs[(m4 + 2) * HD + d0];
            float4 v3 = *(const float4*)&vs[(m4 + 3) * HD + d0];
            acc0.x += s0.x * v0.x + s0.y * v1.x + s0.z * v2.x + s0.w * v3.x;
            acc0.y += s0.x * v0.y + s0.y * v1.y + s0.z * v2.y + s0.w * v3.y;
            acc0.z += s0.x * v0.z + s0.y * v1.z + s0.z * v2.z + s0.w * v3.z;
            acc0.w += s0.x * v0.w + s0.y * v1.w + s0.z * v2.w + s0.w * v3.w;
            acc1.x += s1.x * v0.x + s1.y * v1.x + s1.z * v2.x + s1.w * v3.x;
            acc1.y += s1.x * v0.y + s1.y * v1.y + s1.z * v2.y + s1.w * v3.y;
            acc1.z += s1.x * v0.z + s1.y * v1.z + s1.z * v2.z + s1.w * v3.z;
            acc1.w += s1.x * v0.w + s1.y * v1.w + s1.z * v2.w + s1.w * v3.w;
        }
        {
            float s0 = S[n0][48];
            float s1 = S[n1][48];
            float4 v = *(const float4*)&vs[48 * HD + d0];
            acc0.x += s0 * v.x; acc0.y += s0 * v.y;
            acc0.z += s0 * v.z; acc0.w += s0 * v.w;
            acc1.x += s1 * v.x; acc1.y += s1 * v.y;
            acc1.z += s1 * v.z; acc1.w += s1 * v.w;
        }
        float* o0 = g_att + (size_t)(b * NTOK + n0) * DIM + h * HD + d0;
        *(float4*)o0 = acc0;
        if (n1ok) *(float4*)(o0 + DIM) = acc1;
    }
}

// ---------------------------------------------------------------------------
// Kernel 3: projection GEMM — cp.async B staging, vectorized epilogue.
// ---------------------------------------------------------------------------
__global__ __launch_bounds__(256) void proj_gemm_db(const float* __restrict__ B,
                                                    const float* __restrict__ bias,
                                                    float* __restrict__ out) {
    __shared__ __align__(16) float As[2][BK][128];
    __shared__ __align__(16) float Bs[2][BK][128];

    const int tid  = threadIdx.x;
    const int lane = tid & 31;
    const int warp = tid >> 5;
    const int tRow = (warp >> 1) * 4 + (lane >> 3);
    const int tCol = (warp & 1) * 8 + (lane & 7);
    const int wn   = warp & 1;
    const int cc   = lane & 7;

    const int ar = tid >> 1;
    const int ac = (tid & 1) << 3;
    const int bk = tid >> 4;
    const int bc = (tid & 15) << 3;
    const int bpo = ((bc >> 6) << 6) | (((bc >> 3) & 7) << 2);

    const float* Abase = g_att + (size_t)blockIdx.y * 128 * DIM + (size_t)ar * DIM + ac;
    const float* Bbase = B + (size_t)bk * DIM + blockIdx.x * 128 + bc;

    float acc[8][8];
#pragma unroll
    for (int i = 0; i < 8; i++)
#pragma unroll
        for (int j = 0; j < 8; j++) acc[i][j] = 0.f;

    {
        __pipeline_memcpy_async(&Bs[0][bk][bpo],      Bbase,     16);
        __pipeline_memcpy_async(&Bs[0][bk][bpo + 32], Bbase + 4, 16);
        __pipeline_commit();
        float4 a0 = *(const float4*)(Abase);
        float4 a1 = *(const float4*)(Abase + 4);
        As[0][ac + 0][ar] = a0.x; As[0][ac + 1][ar] = a0.y;
        As[0][ac + 2][ar] = a0.z; As[0][ac + 3][ar] = a0.w;
        As[0][ac + 4][ar] = a1.x; As[0][ac + 5][ar] = a1.y;
        As[0][ac + 6][ar] = a1.z; As[0][ac + 7][ar] = a1.w;
        __pipeline_wait_prior(0);
    }
    __syncthreads();

    for (int ch = 0; ch < NCH; ch++) {
        const int cb = ch & 1;
        const int nb = cb ^ 1;

        float4 pa0, pa1;
        if (ch + 1 < NCH) {
            const float* bsrc = Bbase + (size_t)(ch + 1) * BK * DIM;
            __pipeline_memcpy_async(&Bs[nb][bk][bpo],      bsrc,     16);
            __pipeline_memcpy_async(&Bs[nb][bk][bpo + 32], bsrc + 4, 16);
            __pipeline_commit();
            pa0 = *(const float4*)(Abase + (ch + 1) * BK);
            pa1 = *(const float4*)(Abase + (ch + 1) * BK + 4);
        }

#pragma unroll
        for (int k = 0; k < BK; k++) {
            float rM[8], rN[8];
            float4 m0 = *(const float4*)&As[cb][k][tRow * 8];
            float4 m1 = *(const float4*)&As[cb][k][tRow * 8 + 4];
            float4 n0 = *(const float4*)&Bs[cb][k][wn * 64 + cc * 4];
            float4 n1 = *(const float4*)&Bs[cb][k][wn * 64 + 32 + cc * 4];
            rM[0] = m0.x; rM[1] = m0.y; rM[2] = m0.z; rM[3] = m0.w;
            rM[4] = m1.x; rM[5] = m1.y; rM[6] = m1.z; rM[7] = m1.w;
            rN[0] = n0.x; rN[1] = n0.y; rN[2] = n0.z; rN[3] = n0.w;
            rN[4] = n1.x; rN[5] = n1.y; rN[6] = n1.z; rN[7] = n1.w;
#pragma unroll
            for (int i = 0; i < 8; i++)
#pragma unroll
                for (int j = 0; j < 8; j++) acc[i][j] += rM[i] * rN[j];
        }

        if (ch + 1 < NCH) {
            As[nb][ac + 0][ar] = pa0.x; As[nb][ac + 1][ar] = pa0.y;
            As[nb][ac + 2][ar] = pa0.z; As[nb][ac + 3][ar] = pa0.w;
            As[nb][ac + 4][ar] = pa1.x; As[nb][ac + 5][ar] = pa1.y;
            As[nb][ac + 6][ar] = pa1.z; As[nb][ac + 7][ar] = pa1.w;
            __pipeline_wait_prior(0);
        }
        __syncthreads();
    }

    const int col0 = blockIdx.x * 128 + tCol * 8;
    float4 bx = *(const float4*)&bias[col0];
    float4 by = *(const float4*)&bias[col0 + 4];
#pragma unroll
    for (int i = 0; i < 8; i++) {
        int row = blockIdx.y * 128 + tRow * 8 + i;
        float4 v0 = make_float4(acc[i][0] + bx.x, acc[i][1] + bx.y,
                                acc[i][2] + bx.z, acc[i][3] + bx.w);
        float4 v1 = make_float4(acc[i][4] + by.x, acc[i][5] + by.y,
                                acc[i][6] + by.z, acc[i][7] + by.w);
        *(float4*)&out[(size_t)row * DIM + col0]     = v0;
        *(float4*)&out[(size_t)row * DIM + col0 + 4] = v1;
    }
}

// ---------------------------------------------------------------------------
// Inputs: x, w_qkv, b_qkv, rpb_table, w_proj, b_proj, rel_index
// ---------------------------------------------------------------------------
extern "C" void kernel_launch(void* const* d_in, const int* in_sizes, int n_in,
                              void* d_out, int out_size) {
    const float* x      = (const float*)d_in[0];
    const float* w_qkv  = (const float*)d_in[1];
    const float* b_qkv  = (const float*)d_in[2];
    const float* rpb    = (const float*)d_in[3];
    const float* w_proj = (const float*)d_in[4];
    const float* b_proj = (const float*)d_in[5];
    const int*   rel    = (const int*)d_in[6];
    float* out = (float*)d_out;

    bias_precompute<<<(HEADS * NSQ + 255) / 256, 256>>>(rpb, rel);

    dim3 grid1(THREEC / 128, M_TOT / 128);   // (12, 784)
    qkv_gemm_db<<<grid1, 256>>>(x, w_qkv, b_qkv);

    attn_kernel<<<BW * HEADS, 256>>>();

    dim3 grid3(DIM / 128, M_TOT / 128);      // (4, 784)
    proj_gemm_db<<<grid3, 256>>>(w_proj, b_proj, out);
}

// round 17
// speedup vs baseline: 1.0168x; 1.0168x over previous
#include <cuda_runtime.h>
#include <cuda_bf16.h>

// Problem constants (Swin window attention)
#define WIN    7
#define NTOK   49
#define DIM    512
#define HEADS  16
#define HD     32
#define BW     2048
#define M_TOT  (BW * NTOK)   // 100352
#define THREEC 1536
#define NSQ    (NTOK * NTOK) // 2401

#define BK     16
#define NCH    (DIM / BK)    // 32 K-chunks

// Scratch (allocation-free: __device__ globals)
__device__ float g_q[BW * HEADS * NTOK * HD];
__device__ float g_k[BW * HEADS * NTOK * HD];
__device__ float g_v[BW * HEADS * NTOK * HD];
__device__ float g_att[M_TOT * DIM];
__device__ float g_bias[HEADS * NSQ];      // precomputed rpb[rel[nm]*16+h]

// ---------------------------------------------------------------------------
// Kernel 0: bias precompute. g_bias[h][nm] = rpb[rel[nm]*HEADS + h].
// ---------------------------------------------------------------------------
__global__ void bias_precompute(const float* __restrict__ rpb,
                                const int* __restrict__ rel) {
    int t = blockIdx.x * 256 + threadIdx.x;
    if (t < HEADS * NSQ) {
        int h  = t / NSQ;
        int nm = t - h * NSQ;
        g_bias[t] = rpb[rel[nm] * HEADS + h];
    }
}

// ---------------------------------------------------------------------------
// Kernel 1: QKV GEMM — round-15 proven version (register-staged double
// buffer, BK=16, permuted B smem, vectorized scatter epilogue).
// ---------------------------------------------------------------------------
__global__ __launch_bounds__(256) void qkv_gemm_db(const float* __restrict__ A,
                                                   const float* __restrict__ B,
                                                   const float* __restrict__ bias) {
    __shared__ __align__(16) float As[2][BK][128];
    __shared__ __align__(16) float Bs[2][BK][128];   // permuted

    const int tid  = threadIdx.x;
    const int lane = tid & 31;
    const int warp = tid >> 5;
    const int tRow = (warp >> 1) * 4 + (lane >> 3);
    const int tCol = (warp & 1) * 8 + (lane & 7);
    const int wn   = warp & 1;
    const int cc   = lane & 7;

    const int ar = tid >> 1;
    const int ac = (tid & 1) << 3;
    const int bk = tid >> 4;
    const int bc = (tid & 15) << 3;
    const int bpo = ((bc >> 6) << 6) | (((bc >> 3) & 7) << 2);

    const float* Abase = A + (size_t)blockIdx.y * 128 * DIM + (size_t)ar * DIM + ac;
    const float* Bbase = B + (size_t)bk * THREEC + blockIdx.x * 128 + bc;

    float acc[8][8];
#pragma unroll
    for (int i = 0; i < 8; i++)
#pragma unroll
        for (int j = 0; j < 8; j++) acc[i][j] = 0.f;

    {
        float4 a0 = *(const float4*)(Abase);
        float4 a1 = *(const float4*)(Abase + 4);
        As[0][ac + 0][ar] = a0.x; As[0][ac + 1][ar] = a0.y;
        As[0][ac + 2][ar] = a0.z; As[0][ac + 3][ar] = a0.w;
        As[0][ac + 4][ar] = a1.x; As[0][ac + 5][ar] = a1.y;
        As[0][ac + 6][ar] = a1.z; As[0][ac + 7][ar] = a1.w;
        *(float4*)&Bs[0][bk][bpo]      = *(const float4*)(Bbase);
        *(float4*)&Bs[0][bk][bpo + 32] = *(const float4*)(Bbase + 4);
    }
    __syncthreads();

    for (int ch = 0; ch < NCH; ch++) {
        const int cb = ch & 1;
        const int nb = cb ^ 1;

        float4 pa0, pa1, pb0, pb1;
        if (ch + 1 < NCH) {
            pa0 = *(const float4*)(Abase + (ch + 1) * BK);
            pa1 = *(const float4*)(Abase + (ch + 1) * BK + 4);
            pb0 = *(const float4*)(Bbase + (size_t)(ch + 1) * BK * THREEC);
            pb1 = *(const float4*)(Bbase + (size_t)(ch + 1) * BK * THREEC + 4);
        }

#pragma unroll
        for (int k = 0; k < BK; k++) {
            float rM[8], rN[8];
            float4 m0 = *(const float4*)&As[cb][k][tRow * 8];
            float4 m1 = *(const float4*)&As[cb][k][tRow * 8 + 4];
            float4 n0 = *(const float4*)&Bs[cb][k][wn * 64 + cc * 4];
            float4 n1 = *(const float4*)&Bs[cb][k][wn * 64 + 32 + cc * 4];
            rM[0] = m0.x; rM[1] = m0.y; rM[2] = m0.z; rM[3] = m0.w;
            rM[4] = m1.x; rM[5] = m1.y; rM[6] = m1.z; rM[7] = m1.w;
            rN[0] = n0.x; rN[1] = n0.y; rN[2] = n0.z; rN[3] = n0.w;
            rN[4] = n1.x; rN[5] = n1.y; rN[6] = n1.z; rN[7] = n1.w;
#pragma unroll
            for (int i = 0; i < 8; i++)
#pragma unroll
                for (int j = 0; j < 8; j++) acc[i][j] += rM[i] * rN[j];
        }

        if (ch + 1 < NCH) {
            As[nb][ac + 0][ar] = pa0.x; As[nb][ac + 1][ar] = pa0.y;
            As[nb][ac + 2][ar] = pa0.z; As[nb][ac + 3][ar] = pa0.w;
            As[nb][ac + 4][ar] = pa1.x; As[nb][ac + 5][ar] = pa1.y;
            As[nb][ac + 6][ar] = pa1.z; As[nb][ac + 7][ar] = pa1.w;
            *(float4*)&Bs[nb][bk][bpo]      = pb0;
            *(float4*)&Bs[nb][bk][bpo + 32] = pb1;
        }
        __syncthreads();
    }

    const float scale = 0.17677669529663687f;  // 32^-0.5
    const int col0 = blockIdx.x * 128 + tCol * 8;
    const int s    = col0 >> 9;
    const int rem  = col0 & 511;
    const int hh   = rem >> 5;
    const int dd0  = rem & 31;
    float4 bx = *(const float4*)&bias[col0];
    float4 by = *(const float4*)&bias[col0 + 4];

#pragma unroll
    for (int i = 0; i < 8; i++) {
        int row = blockIdx.y * 128 + tRow * 8 + i;
        int b = row / NTOK;
        int n = row - b * NTOK;
        float4 v0 = make_float4(acc[i][0] + bx.x, acc[i][1] + bx.y,
                                acc[i][2] + bx.z, acc[i][3] + bx.w);
        float4 v1 = make_float4(acc[i][4] + by.x, acc[i][5] + by.y,
                                acc[i][6] + by.z, acc[i][7] + by.w);
        int idx = (((b * HEADS + hh) * NTOK) + n) * HD + dd0;
        if (s == 0) {
            v0.x *= scale; v0.y *= scale; v0.z *= scale; v0.w *= scale;
            v1.x *= scale; v1.y *= scale; v1.z *= scale; v1.w *= scale;
            *(float4*)&g_q[idx] = v0;
            *(float4*)&g_q[idx + 4] = v1;
        } else if (s == 1) {
            *(float4*)&g_k[idx] = v0;
            *(float4*)&g_k[idx + 4] = v1;
        } else {
            *(float4*)&g_v[idx] = v0;
            *(float4*)&g_v[idx + 4] = v1;
        }
    }
}

// ---------------------------------------------------------------------------
// Kernel 2: attention, split 2 blocks per (b,h): rows [0,25) and [25,49).
// Halves per-block serial latency, doubles block-level parallelism.
// ---------------------------------------------------------------------------
#define NROWS0 25

__global__ __launch_bounds__(256) void attn_kernel() {
    __shared__ __align__(16) float qs[NROWS0 * HD];
    __shared__ __align__(16) float kst[HD][52];
    __shared__ __align__(16) float vs[NTOK * HD];
    __shared__ __align__(16) float S[NROWS0][52];

    const int bh2  = blockIdx.x;
    const int bh   = bh2 >> 1;
    const int half = bh2 & 1;
    const int h    = bh & (HEADS - 1);
    const int b    = bh >> 4;
    const int tid  = threadIdx.x;

    const int n_start = half * NROWS0;            // 0 or 25
    const int n_cnt   = half ? (NTOK - NROWS0) : NROWS0;   // 24 or 25
    const float* bias_h = g_bias + h * NSQ + n_start * NTOK;

    const int base = bh * NTOK * HD;
    // K (transposed) and V: all 49 rows
    for (int i = tid; i < NTOK * HD; i += 256) {
        int n = i >> 5;
        int d = i & 31;
        kst[d][n] = g_k[base + i];
        vs[i] = g_v[base + i];
    }
    // Q: only this block's rows
    for (int i = tid; i < n_cnt * HD; i += 256) {
        qs[i] = g_q[base + n_start * HD + i];
    }
    if (tid < 128) {                 // zero kst pad cols 49..51
        int d = tid >> 2;
        int c = tid & 3;
        if (c < 3) kst[d][49 + c] = 0.f;
    }
    __syncthreads();

    // ---- scores: 13 local-n-tiles x 13 m-tiles, 2n x 4m, float4 q ----
    if (tid < 169) {
        int ln0 = (tid / 13) * 2;
        int m0  = (tid % 13) * 4;
        if (ln0 < n_cnt) {
            bool n1ok = (ln0 + 1 < n_cnt);
            int ln1 = n1ok ? ln0 + 1 : ln0;
            float a0[4] = {0.f, 0.f, 0.f, 0.f};
            float a1[4] = {0.f, 0.f, 0.f, 0.f};
#pragma unroll
            for (int d0 = 0; d0 < HD; d0 += 4) {
                float4 qa = *(const float4*)&qs[ln0 * HD + d0];
                float4 qb = *(const float4*)&qs[ln1 * HD + d0];
                float4 k0 = *(const float4*)&kst[d0 + 0][m0];
                float4 k1 = *(const float4*)&kst[d0 + 1][m0];
                float4 k2 = *(const float4*)&kst[d0 + 2][m0];
                float4 k3 = *(const float4*)&kst[d0 + 3][m0];
                a0[0] += qa.x * k0.x + qa.y * k1.x + qa.z * k2.x + qa.w * k3.x;
                a0[1] += qa.x * k0.y + qa.y * k1.y + qa.z * k2.y + qa.w * k3.y;
                a0[2] += qa.x * k0.z + qa.y * k1.z + qa.z * k2.z + qa.w * k3.z;
                a0[3] += qa.x * k0.w + qa.y * k1.w + qa.z * k2.w + qa.w * k3.w;
                a1[0] += qb.x * k0.x + qb.y * k1.x + qb.z * k2.x + qb.w * k3.x;
                a1[1] += qb.x * k0.y + qb.y * k1.y + qb.z * k2.y + qb.w * k3.y;
                a1[2] += qb.x * k0.z + qb.y * k1.z + qb.z * k2.z + qb.w * k3.z;
                a1[3] += qb.x * k0.w + qb.y * k1.w + qb.z * k2.w + qb.w * k3.w;
            }
#pragma unroll
            for (int j = 0; j < 4; j++) {
                int m = m0 + j;
                if (m < NTOK) {
                    S[ln0][m] = a0[j] + bias_h[ln0 * NTOK + m];
                    if (n1ok)
                        S[ln0 + 1][m] = a1[j] + bias_h[(ln0 + 1) * NTOK + m];
                }
            }
        }
    }
    __syncthreads();

    // ---- softmax: warp per local row ----
    {
        const int warp = tid >> 5;
        const int lane = tid & 31;
        for (int n = warp; n < n_cnt; n += 8) {
            float v0 = S[n][lane];
            bool hi = (lane + 32 < NTOK);
            float v1 = hi ? S[n][lane + 32] : -1e30f;
            float mx = fmaxf(v0, v1);
#pragma unroll
            for (int o = 16; o; o >>= 1) mx = fmaxf(mx, __shfl_xor_sync(0xffffffffu, mx, o));
            float e0 = __expf(v0 - mx);
            float e1 = hi ? __expf(v1 - mx) : 0.f;
            float sum = e0 + e1;
#pragma unroll
            for (int o = 16; o; o >>= 1) sum += __shfl_xor_sync(0xffffffffu, sum, o);
            float inv = 1.f / sum;
            S[n][lane] = e0 * inv;
            if (hi) S[n][lane + 32] = e1 * inv;
        }
    }
    __syncthreads();

    // ---- PV: local n x 8 d4-groups, float4 S ----
    if (tid < n_cnt * 8) {
        int ln = tid >> 3;
        int d0 = (tid & 7) << 2;
        float4 acc = make_float4(0.f, 0.f, 0.f, 0.f);
#pragma unroll 4
        for (int m4 = 0; m4 < 48; m4 += 4) {
            float4 s4 = *(const float4*)&S[ln][m4];
            float4 v0 = *(const float4*)&vs[(m4 + 0) * HD + d0];
            float4 v1 = *(const float4*)&vs[(m4 + 1) * HD + d0];
            float4 v2 = *(const float4*)&vs[(m4 + 2) * HD + d0];
            float4 v3 = *(const float4*)&vs[(m4 + 3) * HD + d0];
            acc.x += s4.x * v0.x + s4.y * v1.x + s4.z * v2.x + s4.w * v3.x;
            acc.y += s4.x * v0.y + s4.y * v1.y + s4.z * v2.y + s4.w * v3.y;
            acc.z += s4.x * v0.z + s4.y * v1.z + s4.z * v2.z + s4.w * v3.z;
            acc.w += s4.x * v0.w + s4.y * v1.w + s4.z * v2.w + s4.w * v3.w;
        }
        {
            float s = S[ln][48];
            float4 v = *(const float4*)&vs[48 * HD + d0];
            acc.x += s * v.x; acc.y += s * v.y;
            acc.z += s * v.z; acc.w += s * v.w;
        }
        *(float4*)&g_att[(size_t)(b * NTOK + n_start + ln) * DIM + h * HD + d0] = acc;
    }
}

// ---------------------------------------------------------------------------
// Kernel 3: projection GEMM — round-15 proven version.
// ---------------------------------------------------------------------------
__global__ __launch_bounds__(256) void proj_gemm_db(const float* __restrict__ B,
                                                    const float* __restrict__ bias,
                                                    float* __restrict__ out) {
    __shared__ __align__(16) float As[2][BK][128];
    __shared__ __align__(16) float Bs[2][BK][128];

    const int tid  = threadIdx.x;
    const int lane = tid & 31;
    const int warp = tid >> 5;
    const int tRow = (warp >> 1) * 4 + (lane >> 3);
    const int tCol = (warp & 1) * 8 + (lane & 7);
    const int wn   = warp & 1;
    const int cc   = lane & 7;

    const int ar = tid >> 1;
    const int ac = (tid & 1) << 3;
    const int bk = tid >> 4;
    const int bc = (tid & 15) << 3;
    const int bpo = ((bc >> 6) << 6) | (((bc >> 3) & 7) << 2);

    const float* Abase = g_att + (size_t)blockIdx.y * 128 * DIM + (size_t)ar * DIM + ac;
    const float* Bbase = B + (size_t)bk * DIM + blockIdx.x * 128 + bc;

    float acc[8][8];
#pragma unroll
    for (int i = 0; i < 8; i++)
#pragma unroll
        for (int j = 0; j < 8; j++) acc[i][j] = 0.f;

    {
        float4 a0 = *(const float4*)(Abase);
        float4 a1 = *(const float4*)(Abase + 4);
        As[0][ac + 0][ar] = a0.x; As[0][ac + 1][ar] = a0.y;
        As[0][ac + 2][ar] = a0.z; As[0][ac + 3][ar] = a0.w;
        As[0][ac + 4][ar] = a1.x; As[0][ac + 5][ar] = a1.y;
        As[0][ac + 6][ar] = a1.z; As[0][ac + 7][ar] = a1.w;
        *(float4*)&Bs[0][bk][bpo]      = *(const float4*)(Bbase);
        *(float4*)&Bs[0][bk][bpo + 32] = *(const float4*)(Bbase + 4);
    }
    __syncthreads();

    for (int ch = 0; ch < NCH; ch++) {
        const int cb = ch & 1;
        const int nb = cb ^ 1;

        float4 pa0, pa1, pb0, pb1;
        if (ch + 1 < NCH) {
            pa0 = *(const float4*)(Abase + (ch + 1) * BK);
            pa1 = *(const float4*)(Abase + (ch + 1) * BK + 4);
            pb0 = *(const float4*)(Bbase + (size_t)(ch + 1) * BK * DIM);
            pb1 = *(const float4*)(Bbase + (size_t)(ch + 1) * BK * DIM + 4);
        }

#pragma unroll
        for (int k = 0; k < BK; k++) {
            float rM[8], rN[8];
            float4 m0 = *(const float4*)&As[cb][k][tRow * 8];
            float4 m1 = *(const float4*)&As[cb][k][tRow * 8 + 4];
            float4 n0 = *(const float4*)&Bs[cb][k][wn * 64 + cc * 4];
            float4 n1 = *(const float4*)&Bs[cb][k][wn * 64 + 32 + cc * 4];
            rM[0] = m0.x; rM[1] = m0.y; rM[2] = m0.z; rM[3] = m0.w;
            rM[4] = m1.x; rM[5] = m1.y; rM[6] = m1.z; rM[7] = m1.w;
            rN[0] = n0.x; rN[1] = n0.y; rN[2] = n0.z; rN[3] = n0.w;
            rN[4] = n1.x; rN[5] = n1.y; rN[6] = n1.z; rN[7] = n1.w;
#pragma unroll
            for (int i = 0; i < 8; i++)
#pragma unroll
                for (int j = 0; j < 8; j++) acc[i][j] += rM[i] * rN[j];
        }

        if (ch + 1 < NCH) {
            As[nb][ac + 0][ar] = pa0.x; As[nb][ac + 1][ar] = pa0.y;
            As[nb][ac + 2][ar] = pa0.z; As[nb][ac + 3][ar] = pa0.w;
            As[nb][ac + 4][ar] = pa1.x; As[nb][ac + 5][ar] = pa1.y;
            As[nb][ac + 6][ar] = pa1.z; As[nb][ac + 7][ar] = pa1.w;
            *(float4*)&Bs[nb][bk][bpo]      = pb0;
            *(float4*)&Bs[nb][bk][bpo + 32] = pb1;
        }
        __syncthreads();
    }

    const int col0 = blockIdx.x * 128 + tCol * 8;
    float4 bx = *(const float4*)&bias[col0];
    float4 by = *(const float4*)&bias[col0 + 4];
#pragma unroll
    for (int i = 0; i < 8; i++) {
        int row = blockIdx.y * 128 + tRow * 8 + i;
        float4 v0 = make_float4(acc[i][0] + bx.x, acc[i][1] + bx.y,
                                acc[i][2] + bx.z, acc[i][3] + bx.w);
        float4 v1 = make_float4(acc[i][4] + by.x, acc[i][5] + by.y,
                                acc[i][6] + by.z, acc[i][7] + by.w);
        *(float4*)&out[(size_t)row * DIM + col0]     = v0;
        *(float4*)&out[(size_t)row * DIM + col0 + 4] = v1;
    }
}

// ---------------------------------------------------------------------------
// Inputs: x, w_qkv, b_qkv, rpb_table, w_proj, b_proj, rel_index
// ---------------------------------------------------------------------------
extern "C" void kernel_launch(void* const* d_in, const int* in_sizes, int n_in,
                              void* d_out, int out_size) {
    const float* x      = (const float*)d_in[0];
    const float* w_qkv  = (const float*)d_in[1];
    const float* b_qkv  = (const float*)d_in[2];
    const float* rpb    = (const float*)d_in[3];
    const float* w_proj = (const float*)d_in[4];
    const float* b_proj = (const float*)d_in[5];
    const int*   rel    = (const int*)d_in[6];
    float* out = (float*)d_out;

    bias_precompute<<<(HEADS * NSQ + 255) / 256, 256>>>(rpb, rel);

    dim3 grid1(THREEC / 128, M_TOT / 128);   // (12, 784)
    qkv_gemm_db<<<grid1, 256>>>(x, w_qkv, b_qkv);

    attn_kernel<<<BW * HEADS * 2, 256>>>();

    dim3 grid3(DIM / 128, M_TOT / 128);      // (4, 784)
    proj_gemm_db<<<grid3, 256>>>(w_proj, b_proj, out);
}